// round 5
// baseline (speedup 1.0000x reference)
#include <cuda_runtime.h>
#include <cuda_bf16.h>
#include <cstdint>

// out[128,1024] = x[128,1024] @ (w_pos - w_neg)[1024,1024] + (b_pos - b_neg)
// Memristor scaling cancels exactly (G_OFF in the differential pair, k_cond &
// K_V in the rescale; max_w never needed).
// 3-term bf16 hi/lo emulation on HMMA (baseline PTX mma.sync):
//   x = xh+xl, d = dh+dl;  out ~= xh@dh + xh@dl + xl@dh   (xl@dl ~2^-16)
//
// Round 5: no split-K partials / no reduce kernel. Init kernel writes the bias
// diff into d_out; GEMM epilogue accumulates with red.global.add.v2.f32.
// 256 CTAs (2/SM) so load/epilogue phases overlap compute across CTAs.

#define BATCH 128
#define NIN   1024
#define NOUT  1024
#define KSPLIT 16
#define KCHUNK 64       // NIN / KSPLIT
#define TILE_N 64
#define NT 16           // NOUT / TILE_N
#define RA 144          // A smem row stride bytes (64 bf16 = 128B + 16 pad)
#define RB 144          // B smem row stride bytes (64 bf16 = 128B + 16 pad)

__device__ __forceinline__ uint32_t smem_u32(const void* p) {
    uint32_t a;
    asm("{ .reg .u64 t; cvta.to.shared.u64 t, %1; cvt.u32.u64 %0, t; }" : "=r"(a) : "l"(p));
    return a;
}

__device__ __forceinline__ void split_hl(float v, uint16_t& h, uint16_t& l) {
    __nv_bfloat16 bh = __float2bfloat16(v);
    h = __bfloat16_as_ushort(bh);
    float r = v - __bfloat162float(bh);
    l = __bfloat16_as_ushort(__float2bfloat16(r));
}

__device__ __forceinline__ void ldsm4(uint32_t* r, uint32_t a) {
    asm volatile("ldmatrix.sync.aligned.m8n8.x4.shared.b16 {%0,%1,%2,%3}, [%4];"
                 : "=r"(r[0]), "=r"(r[1]), "=r"(r[2]), "=r"(r[3]) : "r"(a));
}
__device__ __forceinline__ void ldsm4t(uint32_t* r, uint32_t a) {
    asm volatile("ldmatrix.sync.aligned.m8n8.x4.trans.shared.b16 {%0,%1,%2,%3}, [%4];"
                 : "=r"(r[0]), "=r"(r[1]), "=r"(r[2]), "=r"(r[3]) : "r"(a));
}
__device__ __forceinline__ void mma16816(float* d, const uint32_t* a,
                                         uint32_t b0, uint32_t b1) {
    asm volatile("mma.sync.aligned.m16n8k16.row.col.f32.bf16.bf16.f32 "
                 "{%0,%1,%2,%3}, {%4,%5,%6,%7}, {%8,%9}, {%0,%1,%2,%3};"
                 : "+f"(d[0]), "+f"(d[1]), "+f"(d[2]), "+f"(d[3])
                 : "r"(a[0]), "r"(a[1]), "r"(a[2]), "r"(a[3]), "r"(b0), "r"(b1));
}
__device__ __forceinline__ void red_add_v2(float* p, float a, float b) {
    asm volatile("red.global.add.v2.f32 [%0], {%1, %2};"
                 :: "l"(p), "f"(a), "f"(b) : "memory");
}

// ---- init: out = b_pos - b_neg broadcast over batch rows ----
extern "C" __global__ void __launch_bounds__(256)
memr_init_kernel(const float* __restrict__ bp,
                 const float* __restrict__ bn,
                 float* __restrict__ out) {
    int id   = blockIdx.x * 256 + threadIdx.x;   // 0..32767
    int base = id * 4;
    int o    = base & (NOUT - 1);
    float4 vp = *reinterpret_cast<const float4*>(bp + o);
    float4 vn = *reinterpret_cast<const float4*>(bn + o);
    *reinterpret_cast<float4*>(out + base) =
        make_float4(vp.x - vn.x, vp.y - vn.y, vp.z - vn.z, vp.w - vn.w);
}

extern "C" __global__ void __launch_bounds__(256, 2)
memr_gemm_hmma(const float* __restrict__ x,
               const float* __restrict__ wp,
               const float* __restrict__ wn,
               float* __restrict__ out) {
    extern __shared__ char smem_raw[];
    const uint32_t Ah = smem_u32(smem_raw);       // xh [128 b][64 k] bf16
    const uint32_t Al = Ah + 128 * RA;            // xl
    const uint32_t Bh = Al + 128 * RA;            // dh [64 k][64 o] bf16
    const uint32_t Bl = Bh + 64 * RB;             // dl

    const int t  = threadIdx.x;
    const int jt = blockIdx.x;        // N tile (64 cols)
    const int ks = blockIdx.y;        // K split (64 k)
    const int k0 = ks * KCHUNK;
    const int j0 = jt * TILE_N;

    // ---- x tile: [128 b, k0:k0+64], coalesced float4, hi/lo split ----
#pragma unroll 4
    for (int i = 0; i < 8; i++) {
        int id  = t + 256 * i;
        int row = id >> 4;            // batch row (16 float4 per row)
        int kq  = id & 15;
        float4 v = *reinterpret_cast<const float4*>(x + (size_t)row * NIN + k0 + kq * 4);
        uint16_t h0, h1, h2, h3, l0, l1, l2, l3;
        split_hl(v.x, h0, l0); split_hl(v.y, h1, l1);
        split_hl(v.z, h2, l2); split_hl(v.w, h3, l3);
        uint64_t hv = (uint64_t)((uint32_t)h0 | ((uint32_t)h1 << 16)) |
                      ((uint64_t)((uint32_t)h2 | ((uint32_t)h3 << 16)) << 32);
        uint64_t lv = (uint64_t)((uint32_t)l0 | ((uint32_t)l1 << 16)) |
                      ((uint64_t)((uint32_t)l2 | ((uint32_t)l3 << 16)) << 32);
        uint32_t off = (uint32_t)row * RA + (uint32_t)kq * 8;
        asm volatile("st.shared.b64 [%0], %1;" :: "r"(Ah + off), "l"(hv) : "memory");
        asm volatile("st.shared.b64 [%0], %1;" :: "r"(Al + off), "l"(lv) : "memory");
    }

    // ---- W tile: [64 k, 64 o] row-major coalesced, diff+split ----
#pragma unroll 4
    for (int i = 0; i < 4; i++) {
        int id = t + 256 * i;
        int k  = id >> 4;             // k row (16 float4 per row)
        int oq = id & 15;
        const float4 p = *reinterpret_cast<const float4*>(wp + (size_t)(k0 + k) * NOUT + j0 + oq * 4);
        const float4 n = *reinterpret_cast<const float4*>(wn + (size_t)(k0 + k) * NOUT + j0 + oq * 4);
        uint16_t h0, h1, h2, h3, l0, l1, l2, l3;
        split_hl(p.x - n.x, h0, l0); split_hl(p.y - n.y, h1, l1);
        split_hl(p.z - n.z, h2, l2); split_hl(p.w - n.w, h3, l3);
        uint64_t hv = (uint64_t)((uint32_t)h0 | ((uint32_t)h1 << 16)) |
                      ((uint64_t)((uint32_t)h2 | ((uint32_t)h3 << 16)) << 32);
        uint64_t lv = (uint64_t)((uint32_t)l0 | ((uint32_t)l1 << 16)) |
                      ((uint64_t)((uint32_t)l2 | ((uint32_t)l3 << 16)) << 32);
        uint32_t off = (uint32_t)k * RB + (uint32_t)oq * 8;
        asm volatile("st.shared.b64 [%0], %1;" :: "r"(Bh + off), "l"(hv) : "memory");
        asm volatile("st.shared.b64 [%0], %1;" :: "r"(Bl + off), "l"(lv) : "memory");
    }
    __syncthreads();

    // ---- compute: 8 warps as 4(M) x 2(N); warp tile 32 rows x 32 cols ----
    const int wid  = t >> 5;
    const int lane = t & 31;
    const int wm  = wid >> 1;         // rows 32*wm
    const int wn2 = wid & 1;          // cols 32*wn2

    float acc[2][4][4];
#pragma unroll
    for (int mt = 0; mt < 2; mt++)
#pragma unroll
        for (int n = 0; n < 4; n++)
#pragma unroll
            for (int i = 0; i < 4; i++) acc[mt][n][i] = 0.0f;

    const uint32_t aOff = (uint32_t)(wm * 32 + (lane & 15)) * RA + (uint32_t)((lane >> 4) * 16);
    const uint32_t bOff = (uint32_t)(lane & 15) * RB + (uint32_t)(wn2 * 32 + (lane >> 4) * 8) * 2;
    const uint32_t aH = Ah + aOff, aL = Al + aOff;
    const uint32_t bH = Bh + bOff, bL = Bl + bOff;

#pragma unroll
    for (int s = 0; s < 4; s++) {
        const uint32_t soA = (uint32_t)s * 32;        // 16 bf16 = 32B along k
        const uint32_t soB = (uint32_t)(s * 16) * RB; // 16 k-rows down
        uint32_t ah[2][4], al[2][4];
        ldsm4(ah[0], aH + soA);
        ldsm4(ah[1], aH + 16 * RA + soA);
        ldsm4(al[0], aL + soA);
        ldsm4(al[1], aL + 16 * RA + soA);
        uint32_t bhr[2][4], blr[2][4];
        ldsm4t(bhr[0], bH + soB);
        ldsm4t(bhr[1], bH + soB + 32);    // cols +16
        ldsm4t(blr[0], bL + soB);
        ldsm4t(blr[1], bL + soB + 32);
#pragma unroll
        for (int n = 0; n < 4; n++) {
            const int g = n >> 1, j = n & 1;
            const uint32_t b0h = bhr[g][2 * j], b1h = bhr[g][2 * j + 1];
            const uint32_t b0l = blr[g][2 * j], b1l = blr[g][2 * j + 1];
#pragma unroll
            for (int mt = 0; mt < 2; mt++) {
                mma16816(acc[mt][n], ah[mt], b0h, b1h);
                mma16816(acc[mt][n], ah[mt], b0l, b1l);
                mma16816(acc[mt][n], al[mt], b0h, b1h);
            }
        }
    }

    // ---- epilogue: accumulate warp block 32x32 into out via red.v2 ----
    const int r0 = wm * 32 + (lane >> 2);
    const int c0 = j0 + wn2 * 32 + 2 * (lane & 3);
#pragma unroll
    for (int mt = 0; mt < 2; mt++) {
#pragma unroll
        for (int n = 0; n < 4; n++) {
            int row = r0 + mt * 16;
            int col = c0 + n * 8;
            red_add_v2(out + (size_t)row * NOUT + col, acc[mt][n][0], acc[mt][n][1]);
            red_add_v2(out + (size_t)(row + 8) * NOUT + col, acc[mt][n][2], acc[mt][n][3]);
        }
    }
}

extern "C" void kernel_launch(void* const* d_in, const int* in_sizes, int n_in,
                              void* d_out, int out_size) {
    const float* x  = (const float*)d_in[0];
    const float* wp = (const float*)d_in[1];
    const float* wn = (const float*)d_in[2];
    const float* bp = (const float*)d_in[3];
    const float* bn = (const float*)d_in[4];
    float* out = (float*)d_out;

    const int smem_bytes = 2 * 128 * RA + 2 * 64 * RB;   // 55296
    cudaFuncSetAttribute(memr_gemm_hmma,
                         cudaFuncAttributeMaxDynamicSharedMemorySize, smem_bytes);

    memr_init_kernel<<<128, 256>>>(bp, bn, out);
    dim3 grid(NT, KSPLIT);
    memr_gemm_hmma<<<grid, 256, smem_bytes>>>(x, wp, wn, out);
}